// round 3
// baseline (speedup 1.0000x reference)
#include <cuda_runtime.h>

#define INV_SQRT_2PI 0.3989422804014327f

#define THREADS 256
#define VPT 4                 // float4 per thread per tile
#define TILE (THREADS * VPT)  // 1024 float4 per tile
#define NBLOCKS (148 * 8)     // one full wave at occupancy 8

__device__ __forceinline__ float hess(float x) {
    float t = x * x;
    return (2.0f - 2.0f * t) * (INV_SQRT_2PI * __expf(-0.5f * t));
}

__global__ void __launch_bounds__(THREADS, 8) hess_gelu_kernel(
    const float4* __restrict__ x, float4* __restrict__ out, int ntiles)
{
    // Persistent grid-stride over tiles; within a tile, thread accesses are
    // block-strided so each of the VPT loads is fully coalesced.
    for (int tile = blockIdx.x; tile < ntiles; tile += NBLOCKS) {
        size_t base = (size_t)tile * TILE + threadIdx.x;

        float4 v[VPT];
#pragma unroll
        for (int j = 0; j < VPT; j++) {
            const float4* p = x + base + j * THREADS;
            asm volatile("ld.global.cs.v4.f32 {%0,%1,%2,%3}, [%4];"
                         : "=f"(v[j].x), "=f"(v[j].y), "=f"(v[j].z), "=f"(v[j].w)
                         : "l"(p));
        }

#pragma unroll
        for (int j = 0; j < VPT; j++) {
            v[j].x = hess(v[j].x);
            v[j].y = hess(v[j].y);
            v[j].z = hess(v[j].z);
            v[j].w = hess(v[j].w);
        }

#pragma unroll
        for (int j = 0; j < VPT; j++) {
            float4* p = out + base + j * THREADS;
            asm volatile("st.global.cs.v4.f32 [%0], {%1,%2,%3,%4};"
                         :: "l"(p), "f"(v[j].x), "f"(v[j].y), "f"(v[j].z), "f"(v[j].w)
                         : "memory");
        }
    }
}

extern "C" void kernel_launch(void* const* d_in, const int* in_sizes, int n_in,
                              void* d_out, int out_size)
{
    const float* x = (const float*)d_in[0];
    float* out = (float*)d_out;
    int n = in_sizes[0];       // 268435456
    int n4 = n >> 2;           // 2^26 float4
    int ntiles = n4 / TILE;    // 65536, exact
    hess_gelu_kernel<<<NBLOCKS, THREADS>>>((const float4*)x, (float4*)out, ntiles);
}

// round 4
// speedup vs baseline: 1.1340x; 1.1340x over previous
#include <cuda_runtime.h>

#define INV_SQRT_2PI 0.3989422804014327f

// n = 2^28 floats = 2^26 float4 = 32768 blocks * 256 threads * 8 float4/thread.
#define THREADS 256
#define VPT 8  // float4 per thread

__device__ __forceinline__ float hess(float x) {
    float t = x * x;
    return (2.0f - 2.0f * t) * (INV_SQRT_2PI * __expf(-0.5f * t));
}

__global__ void __launch_bounds__(THREADS) hess_gelu_kernel(
    const float4* __restrict__ x, float4* __restrict__ out)
{
    size_t base = (size_t)blockIdx.x * (THREADS * VPT) + threadIdx.x;

    float4 v[VPT];
#pragma unroll
    for (int j = 0; j < VPT; j++) {
        const float4* p = x + base + j * THREADS;
        asm volatile("ld.global.cs.v4.f32 {%0,%1,%2,%3}, [%4];"
                     : "=f"(v[j].x), "=f"(v[j].y), "=f"(v[j].z), "=f"(v[j].w)
                     : "l"(p));
    }

#pragma unroll
    for (int j = 0; j < VPT; j++) {
        v[j].x = hess(v[j].x);
        v[j].y = hess(v[j].y);
        v[j].z = hess(v[j].z);
        v[j].w = hess(v[j].w);
    }

#pragma unroll
    for (int j = 0; j < VPT; j++) {
        float4* p = out + base + j * THREADS;
        asm volatile("st.global.cs.v4.f32 [%0], {%1,%2,%3,%4};"
                     :: "l"(p), "f"(v[j].x), "f"(v[j].y), "f"(v[j].z), "f"(v[j].w)
                     : "memory");
    }
}

extern "C" void kernel_launch(void* const* d_in, const int* in_sizes, int n_in,
                              void* d_out, int out_size)
{
    const float* x = (const float*)d_in[0];
    float* out = (float*)d_out;
    int n = in_sizes[0];                 // 268435456
    int n4 = n >> 2;                     // 2^26 float4
    int blocks = n4 / (THREADS * VPT);   // 32768, exact
    hess_gelu_kernel<<<blocks, THREADS>>>((const float4*)x, (float4*)out);
}

// round 5
// speedup vs baseline: 1.1347x; 1.0006x over previous
#include <cuda_runtime.h>

#define INV_SQRT_2PI 0.3989422804014327f

// n = 2^28 floats = 2^26 float4 = 16384 blocks * 512 threads * 4 float4/thread.
#define THREADS 512
#define VPT 4  // float4 per thread

__device__ __forceinline__ float hess(float x) {
    float t = x * x;
    return (2.0f - 2.0f * t) * (INV_SQRT_2PI * __expf(-0.5f * t));
}

__global__ void __launch_bounds__(THREADS) hess_gelu_kernel(
    const float4* __restrict__ x, float4* __restrict__ out)
{
    size_t base = (size_t)blockIdx.x * (THREADS * VPT) + threadIdx.x;

    float4 v[VPT];
#pragma unroll
    for (int j = 0; j < VPT; j++) {
        const float4* p = x + base + j * THREADS;
        asm volatile("ld.global.cs.v4.f32 {%0,%1,%2,%3}, [%4];"
                     : "=f"(v[j].x), "=f"(v[j].y), "=f"(v[j].z), "=f"(v[j].w)
                     : "l"(p));
    }

#pragma unroll
    for (int j = 0; j < VPT; j++) {
        v[j].x = hess(v[j].x);
        v[j].y = hess(v[j].y);
        v[j].z = hess(v[j].z);
        v[j].w = hess(v[j].w);
    }

#pragma unroll
    for (int j = 0; j < VPT; j++) {
        float4* p = out + base + j * THREADS;
        asm volatile("st.global.cs.v4.f32 [%0], {%1,%2,%3,%4};"
                     :: "l"(p), "f"(v[j].x), "f"(v[j].y), "f"(v[j].z), "f"(v[j].w)
                     : "memory");
    }
}

extern "C" void kernel_launch(void* const* d_in, const int* in_sizes, int n_in,
                              void* d_out, int out_size)
{
    const float* x = (const float*)d_in[0];
    float* out = (float*)d_out;
    int n = in_sizes[0];                 // 268435456
    int n4 = n >> 2;                     // 2^26 float4
    int blocks = n4 / (THREADS * VPT);   // 16384, exact
    hess_gelu_kernel<<<blocks, THREADS>>>((const float4*)x, (float4*)out);
}

// round 6
// speedup vs baseline: 1.1374x; 1.0024x over previous
#include <cuda_runtime.h>

#define INV_SQRT_2PI 0.3989422804014327f

// n = 2^28 floats = 2^26 float4 = 65536 blocks * 256 threads * 4 float4/thread.
#define THREADS 256
#define VPT 4  // float4 per thread

__device__ __forceinline__ float hess(float x) {
    float t = x * x;
    return (2.0f - 2.0f * t) * (INV_SQRT_2PI * __expf(-0.5f * t));
}

__global__ void __launch_bounds__(THREADS) hess_gelu_kernel(
    const float4* __restrict__ x, float4* __restrict__ out)
{
    // Block-contiguous tile of THREADS*VPT float4s; thread accesses are
    // block-strided so each of the VPT loads is fully coalesced.
    size_t base = (size_t)blockIdx.x * (THREADS * VPT) + threadIdx.x;

    float4 v[VPT];
#pragma unroll
    for (int j = 0; j < VPT; j++) {
        const float4* p = x + base + j * THREADS;
        // streaming load (evict-first): no reuse, keep L2 clean
        asm volatile("ld.global.cs.v4.f32 {%0,%1,%2,%3}, [%4];"
                     : "=f"(v[j].x), "=f"(v[j].y), "=f"(v[j].z), "=f"(v[j].w)
                     : "l"(p));
    }

#pragma unroll
    for (int j = 0; j < VPT; j++) {
        v[j].x = hess(v[j].x);
        v[j].y = hess(v[j].y);
        v[j].z = hess(v[j].z);
        v[j].w = hess(v[j].w);
    }

#pragma unroll
    for (int j = 0; j < VPT; j++) {
        float4* p = out + base + j * THREADS;
        asm volatile("st.global.cs.v4.f32 [%0], {%1,%2,%3,%4};"
                     :: "l"(p), "f"(v[j].x), "f"(v[j].y), "f"(v[j].z), "f"(v[j].w)
                     : "memory");
    }
}

extern "C" void kernel_launch(void* const* d_in, const int* in_sizes, int n_in,
                              void* d_out, int out_size)
{
    const float* x = (const float*)d_in[0];
    float* out = (float*)d_out;
    int n = in_sizes[0];                 // 268435456
    int n4 = n >> 2;                     // 2^26 float4
    int blocks = n4 / (THREADS * VPT);   // 65536, exact
    hess_gelu_kernel<<<blocks, THREADS>>>((const float4*)x, (float4*)out);
}